// round 15
// baseline (speedup 1.0000x reference)
#include <cuda_runtime.h>
#include <cuda_fp16.h>
#include <cstdint>

// ---------------- problem constants ----------------
#define VOCAB 50000
#define EMB   1024
#define HID   2048
#define BATCH 256
#define SEQ   128
#define NG    6144
#define NM    (BATCH*SEQ)   // 32768 (t,b) positions

// Backward packing (12-col units): block = n/12, w = n%12, gate = w>>2, jj = w&3,
//   j = block*4 + jj, wr = j + {0,4096,6144}[gate]   (i,g,o; f unused)
// Forward packing (48-col bands, register-local cell): band = n/48, w = n%48,
//   gate = w>>4, jj = w&15, j = band*16+jj

// ---------------- GEMM tiling (one-shot kernel) ----------------
#define TM 128
#define TN 96
#define DEPTH 4
#define STAGE_A (128*128)              // 16384 B
#define STAGE_B (96*128)               // 12288 B
#define STAGE_BYTES (STAGE_A+STAGE_B)  // 28672 B
#define GEMM_SMEM (DEPTH*STAGE_BYTES)  // 114688 B

// ---------------- recurrence tiling: 148 CTAs = 2 slices x 74 panels ----------------
#define CPS   74                       // CTAs per slice
#define FAT   68                       // CTAs with 7 units (84 cols); rest 6 (72)
#define GOFF  (4*STAGE_BYTES)          // G tile offset        = 114688
#define GPITCH_B 192                   // G tile row pitch bytes (96 halfs)
#define GT_BYTES (128*GPITCH_B)        // 24576
#define SNAP_OFF (GOFF + GT_BYTES)     // 139264
#define SNAP_STRIDE 320                // 80 ints per snapshot slot
#define RECUR_SMEM (SNAP_OFF + 4*SNAP_STRIDE)   // 140544

// ---------------- scratch (__device__ globals) ----------------
__device__ __half g_Xu[(size_t)NM * EMB];
__device__ __half g_Xlast[(size_t)BATCH * EMB];
__device__ __half g_Gu[(size_t)NM * NG + 128];   // +128 pad: recur G prefetch overreads <=48B
__device__ __half g_Whh[(size_t)NG * HID];       // 12-packed
__device__ __half g_Wib[(size_t)NG * EMB];       // 12-packed
__device__ __half g_Wif[(size_t)NG * EMB];       // 48-packed
__device__ float  g_bb[NG];                      // 12-packed
__device__ float  g_bf[NG];                      // 48-packed
__device__ __half g_H[2][(size_t)BATCH * HID];
__device__ int    g_flag[SEQ][2][80];            // per (step, slice, producer cwi)
__device__ int    g_mark[VOCAB];
__device__ int    g_uidmap[VOCAB];
__device__ int    g_tok_of[NM];
__device__ int    g_uid_of[NM];
__device__ int    g_nu;

// ---------------- helpers ----------------
__device__ __forceinline__ uint32_t smem_u32(const void* p) {
    uint32_t a;
    asm("{ .reg .u64 t; cvta.to.shared.u64 t, %1; cvt.u32.u64 %0, t; }" : "=r"(a) : "l"(p));
    return a;
}

#define CP16(saddr, gptr) \
    asm volatile("cp.async.cg.shared.global [%0], [%1], 16;" :: "r"(saddr), "l"(gptr))
#define CP8(saddr, gptr) \
    asm volatile("cp.async.ca.shared.global [%0], [%1], 8;" :: "r"(saddr), "l"(gptr))

#define LDSM4(r, a) \
    asm volatile("ldmatrix.sync.aligned.m8n8.x4.shared.b16 {%0,%1,%2,%3}, [%4];" \
        : "=r"((r)[0]), "=r"((r)[1]), "=r"((r)[2]), "=r"((r)[3]) : "r"(a))

__device__ __forceinline__ void mma_f16(float c[4], const uint32_t a[4],
                                        uint32_t b0, uint32_t b1) {
    asm volatile(
        "mma.sync.aligned.m16n8k16.row.col.f32.f16.f16.f32 "
        "{%0,%1,%2,%3},{%4,%5,%6,%7},{%8,%9},{%0,%1,%2,%3};"
        : "+f"(c[0]), "+f"(c[1]), "+f"(c[2]), "+f"(c[3])
        : "r"(a[0]), "r"(a[1]), "r"(a[2]), "r"(a[3]), "r"(b0), "r"(b1));
}

__device__ __forceinline__ float sigm(float x)  { return 1.f / (1.f + __expf(-x)); }
__device__ __forceinline__ float tanhe(float x) { return 2.f / (1.f + __expf(-2.f * x)) - 1.f; }

__device__ __forceinline__ int gate_row12(int n) {
    int blk = n / 12, w = n - blk * 12;
    int gate = w >> 2, jj = w & 3;
    return blk * 4 + jj + (gate == 0 ? 0 : (gate == 1 ? 4096 : 6144));
}
__device__ __forceinline__ int gate_row48(int n) {
    int band = n / 48, w = n - band * 48;
    int gate = w >> 4, jj = w & 15;
    return band * 16 + jj + (gate == 0 ? 0 : (gate == 1 ? 4096 : 6144));
}
// H column j -> producer CTA (within slice) under the 68x28 + 6x24 j partition
__device__ __forceinline__ int c_of(int j) {
    return j < 1904 ? j / 28 : 68 + (j - 1904) / 24;
}

// ---------------- dedup + prep kernels ----------------
__global__ void reset_all() {
    int i = blockIdx.x * 256 + threadIdx.x;
    if (i < VOCAB) g_mark[i] = 0;
    if (i < SEQ * 2 * 80) ((int*)g_flag)[i] = 0;
    if (i == 0) g_nu = 0;
}

__global__ void claim_tokens(const int* __restrict__ idx) {
    int m = blockIdx.x * 256 + threadIdx.x;
    int t = m >> 8, b = m & 255;
    int tok = idx[b * SEQ + t];
    if ((unsigned)tok >= (unsigned)VOCAB) tok = 0;
    if (atomicCAS(&g_mark[tok], 0, 1) == 0) {
        int u = atomicAdd(&g_nu, 1);
        g_uidmap[tok] = u;
        g_tok_of[u] = tok;
    }
}

__global__ void map_uid(const int* __restrict__ idx) {
    int m = blockIdx.x * 256 + threadIdx.x;
    int t = m >> 8, b = m & 255;
    int tok = idx[b * SEQ + t];
    if ((unsigned)tok >= (unsigned)VOCAB) tok = 0;
    g_uid_of[m] = g_uidmap[tok];
}

__device__ __forceinline__ void copy_row_f2h(const float* __restrict__ src,
                                             __half* __restrict__ dst) {
    const float4* s = (const float4*)src + threadIdx.x * 2;
    float4 v0 = s[0], v1 = s[1];
    __half2 h0 = __floats2half2_rn(v0.x, v0.y), h1 = __floats2half2_rn(v0.z, v0.w);
    __half2 h2 = __floats2half2_rn(v1.x, v1.y), h3 = __floats2half2_rn(v1.z, v1.w);
    ((uint4*)dst)[threadIdx.x] =
        make_uint4(*(uint32_t*)&h0, *(uint32_t*)&h1, *(uint32_t*)&h2, *(uint32_t*)&h3);
}

__global__ void gather_unique(const float* __restrict__ table, __half* __restrict__ dst) {
    int u = blockIdx.x;
    if (u >= g_nu) return;
    copy_row_f2h(table + (size_t)g_tok_of[u] * EMB, dst + (size_t)u * EMB);
}

__global__ void gather_last(const int* __restrict__ idx, const float* __restrict__ table,
                            __half* __restrict__ dst) {
    int b = blockIdx.x;
    int row = idx[b * SEQ + (SEQ - 1)];
    if ((unsigned)row >= (unsigned)VOCAB) row = 0;
    copy_row_f2h(table + (size_t)row * EMB, dst + (size_t)b * EMB);
}

__global__ void pack_weight(__half* __restrict__ dst, const float* __restrict__ src,
                            int K, int pack12) {
    int n = blockIdx.x;
    int wr = pack12 ? gate_row12(n) : gate_row48(n);
    const float4* s = (const float4*)(src + (size_t)wr * K);
    uint4* d = (uint4*)(dst + (size_t)n * K);
    for (int i = threadIdx.x; i < (K >> 3); i += blockDim.x) {
        float4 a = s[i * 2], b = s[i * 2 + 1];
        __half2 h0 = __floats2half2_rn(a.x, a.y), h1 = __floats2half2_rn(a.z, a.w);
        __half2 h2 = __floats2half2_rn(b.x, b.y), h3 = __floats2half2_rn(b.z, b.w);
        d[i] = make_uint4(*(uint32_t*)&h0, *(uint32_t*)&h1, *(uint32_t*)&h2, *(uint32_t*)&h3);
    }
}

__global__ void pack_bias(float* __restrict__ db, const float* __restrict__ bi_b, const float* __restrict__ bh_b,
                          float* __restrict__ df, const float* __restrict__ bi_f, const float* __restrict__ bh_f) {
    int n = blockIdx.x * blockDim.x + threadIdx.x;
    if (n >= NG) return;
    int w12 = gate_row12(n);
    int w48 = gate_row48(n);
    db[n] = bi_b[w12] + bh_b[w12];
    df[n] = bi_f[w48] + bh_f[w48];
}

// ---------------- fragments ----------------
struct Frag  { uint32_t a0[4], a1[4], b0[4], b1[4], b2[4]; };     // one-shot GEMM
struct FragR { uint32_t a[4], b[6][4]; };                          // recurrence

// ---------------- one-shot GEMM (precompute / forward cell) — unchanged ----------------
__global__ __launch_bounds__(256) void lstm_gemm(
    const __half* __restrict__ A, int K, const __half* __restrict__ W,
    const float* __restrict__ bias,
    __half* __restrict__ gout, float* __restrict__ fout,
    int mode, int out_ld)
{
    extern __shared__ char smem[];
    const uint32_t sbase = smem_u32(smem);
    const int tid = threadIdx.x;
    const int lane = tid & 31, warp = tid >> 5;
    const int gid = lane >> 2, tig = lane & 3;
    const int wm = warp & 3, wn = warp >> 2;
    const int bm = (mode == 0) ? blockIdx.y : blockIdx.x;
    const int bn = (mode == 0) ? blockIdx.x : blockIdx.y;
    const int m0 = bm * TM;
    const int j0 = bn * TN;

    if (mode == 0 && m0 >= g_nu) return;

    float acc[2][6][4];
#pragma unroll
    for (int mt = 0; mt < 2; ++mt)
#pragma unroll
        for (int nt = 0; nt < 6; ++nt)
#pragma unroll
            for (int c = 0; c < 4; ++c) acc[mt][nt][c] = 0.f;

    const int ar = wm * 32 + (lane & 15);
    const uint32_t aoff0 = (uint32_t)ar * 128u, aoff1 = aoff0 + 2048u;
    const uint32_t aswz  = (uint32_t)(ar & 7) << 4;
    const uint32_t akh   = ((lane >> 4) & 1) << 4;
    const int brb = wn * 48 + (lane & 7) + ((lane >> 4) << 3);
    const uint32_t bswz = (uint32_t)(brb & 7) << 4;
    const uint32_t bkh  = ((lane >> 3) & 1) << 4;
    const uint32_t boff0 = (uint32_t)brb * 128u, boff1 = boff0 + 2048u, boff2 = boff0 + 4096u;

    const int nkt = K >> 6;
    const char* Abase = (const char*)A + (size_t)m0 * 2 * K;
    const char* Bbase = (const char*)W + (size_t)j0 * 2 * K;

    auto fill = [&](int kt) {
        uint32_t st = sbase + (uint32_t)(kt & 3) * STAGE_BYTES;
        const char* Ab = Abase + kt * 128;
        const char* Bb = Bbase + kt * 128;
#pragma unroll
        for (int i = 0; i < 4; ++i) {
            int s = tid + i * 256;
            int row = s >> 3, q = s & 7;
            CP16(st + (uint32_t)(row * 128) + (((uint32_t)(q * 16)) ^ ((uint32_t)(row & 7) << 4)),
                 Ab + (size_t)row * 2 * K + q * 16);
        }
        uint32_t stb = st + STAGE_A;
#pragma unroll
        for (int i = 0; i < 3; ++i) {
            int s = tid + i * 256;
            int row = s >> 3, q = s & 7;
            CP16(stb + (uint32_t)(row * 128) + (((uint32_t)(q * 16)) ^ ((uint32_t)(row & 7) << 4)),
                 Bb + (size_t)row * 2 * K + q * 16);
        }
    };

#pragma unroll
    for (int p = 0; p < DEPTH - 1; ++p) {
        if (p < nkt) fill(p);
        asm volatile("cp.async.commit_group;");
    }

    Frag f[2];
#pragma unroll 1
    for (int kt = 0; kt < nkt; ++kt) {
        asm volatile("cp.async.wait_group %0;" :: "n"(DEPTH - 2));
        __syncthreads();
        if (kt + DEPTH - 1 < nkt) fill(kt + DEPTH - 1);
        asm volatile("cp.async.commit_group;");

        uint32_t st  = sbase + (uint32_t)(kt & 3) * STAGE_BYTES;
        uint32_t stB = st + STAGE_A;
        {
            uint32_t ca = akh ^ aswz, cb = bkh ^ bswz;
            LDSM4(f[0].a0, st + aoff0 + ca);  LDSM4(f[0].a1, st + aoff1 + ca);
            LDSM4(f[0].b0, stB + boff0 + cb); LDSM4(f[0].b1, stB + boff1 + cb); LDSM4(f[0].b2, stB + boff2 + cb);
        }
#pragma unroll
        for (int ks = 0; ks < 4; ++ks) {
            if (ks < 3) {
                int nb = (ks + 1) & 1;
                uint32_t ca = (((uint32_t)((ks + 1) * 32)) | akh) ^ aswz;
                uint32_t cb = (((uint32_t)((ks + 1) * 32)) | bkh) ^ bswz;
                LDSM4(f[nb].a0, st + aoff0 + ca);  LDSM4(f[nb].a1, st + aoff1 + ca);
                LDSM4(f[nb].b0, stB + boff0 + cb); LDSM4(f[nb].b1, stB + boff1 + cb); LDSM4(f[nb].b2, stB + boff2 + cb);
            }
            Frag& c = f[ks & 1];
            mma_f16(acc[0][0], c.a0, c.b0[0], c.b0[1]);  mma_f16(acc[1][0], c.a1, c.b0[0], c.b0[1]);
            mma_f16(acc[0][1], c.a0, c.b0[2], c.b0[3]);  mma_f16(acc[1][1], c.a1, c.b0[2], c.b0[3]);
            mma_f16(acc[0][2], c.a0, c.b1[0], c.b1[1]);  mma_f16(acc[1][2], c.a1, c.b1[0], c.b1[1]);
            mma_f16(acc[0][3], c.a0, c.b1[2], c.b1[3]);  mma_f16(acc[1][3], c.a1, c.b1[2], c.b1[3]);
            mma_f16(acc[0][4], c.a0, c.b2[0], c.b2[1]);  mma_f16(acc[1][4], c.a1, c.b2[0], c.b2[1]);
            mma_f16(acc[0][5], c.a0, c.b2[2], c.b2[3]);  mma_f16(acc[1][5], c.a1, c.b2[2], c.b2[3]);
        }
    }

    if (mode == 0) {
#pragma unroll
        for (int mt = 0; mt < 2; ++mt)
#pragma unroll
            for (int nt = 0; nt < 6; ++nt) {
                int u = m0 + wm * 32 + mt * 16 + gid;
                int n = j0 + wn * 48 + nt * 8 + tig * 2;
                float bv0 = bias[n], bv1 = bias[n + 1];
                __half2 v0 = __floats2half2_rn(acc[mt][nt][0] + bv0, acc[mt][nt][1] + bv1);
                __half2 v1 = __floats2half2_rn(acc[mt][nt][2] + bv0, acc[mt][nt][3] + bv1);
                *(__half2*)&gout[(size_t)u * NG + n]       = v0;
                *(__half2*)&gout[(size_t)(u + 8) * NG + n] = v1;
            }
    } else {
#pragma unroll
        for (int mt = 0; mt < 2; ++mt)
#pragma unroll
            for (int jh = 0; jh < 2; ++jh)
#pragma unroll
                for (int rp = 0; rp < 2; ++rp) {
                    int row = m0 + wm * 32 + mt * 16 + gid + rp * 8;
                    int nb = j0 + wn * 48 + jh * 8 + tig * 2;
                    float hv[2];
#pragma unroll
                    for (int col = 0; col < 2; ++col) {
                        float gi = acc[mt][jh][rp * 2 + col]     + bias[nb + col];
                        float gg = acc[mt][2 + jh][rp * 2 + col] + bias[nb + 16 + col];
                        float go = acc[mt][4 + jh][rp * 2 + col] + bias[nb + 32 + col];
                        hv[col] = sigm(go) * tanhe(sigm(gi) * tanhe(gg));
                    }
                    int j = bn * 32 + wn * 16 + jh * 8 + tig * 2;
                    *(float2*)&fout[(size_t)row * out_ld + j] = make_float2(hv[0], hv[1]);
                }
    }
}

// ---------------- persistent recurrence: 148 CTAs = 2 slices x 74 panels ----------------
__global__ __launch_bounds__(256, 1) void lstm_recur(
    const __half* __restrict__ Gu, const __half* __restrict__ W,
    __half* __restrict__ H0, __half* __restrict__ H1, float* __restrict__ out)
{
    extern __shared__ char smem[];
    const uint32_t sbase = smem_u32(smem);
    const uint32_t gsm = sbase + GOFF;
    __half* GtH = (__half*)(smem + GOFF);
    const uint32_t snap_base = sbase + SNAP_OFF;
    const int* snapI = (const int*)(smem + SNAP_OFF);
    float* Gs = (float*)smem;                      // gates staging [128][92] fp32 (aliases stages 0-1)

    const int tid = threadIdx.x;
    const int lane = tid & 31, warp = tid >> 5;
    const int cid = blockIdx.x;                    // 0..147
    const int x = (cid < CPS) ? 0 : 1;
    const int cwi = cid - x * CPS;
    int u0, nun;
    if (cwi < FAT) { u0 = cwi * 7; nun = 7; }
    else           { u0 = FAT * 7 + (cwi - FAT) * 6; nun = 6; }
    const int n0 = u0 * 12;                        // packed col base in W/Gu
    const int ncols = nun * 12;                    // 84 or 72
    const int j0 = u0 * 4;                         // H column base
    const int njs = nun * 4;                       // 28 or 24
    const int m0 = x * 128;

    // A ldmatrix: warp = 16-row band
    const int ar = warp * 16 + (lane & 15);
    const uint32_t aoff = (uint32_t)ar * 128u;
    const uint32_t aswz = (uint32_t)(ar & 7) << 4;
    const uint32_t akh  = ((lane >> 4) & 1) << 4;
    // B ldmatrix: every warp loads all 6 fi2 groups (rows fi2*16 + pattern)
    const int brl = (lane & 7) + ((lane >> 4) << 3);
    const uint32_t bswz = (uint32_t)(lane & 7) << 4;
    const uint32_t bkh  = ((lane >> 3) & 1) << 4;

    const char* Bbase = (const char*)W + (size_t)n0 * 2 * HID;

#pragma unroll 1
    for (int s = 0; s < SEQ; ++s) {
        const int t = (SEQ - 1) - s;

        // group 0: G tile (indirect; 8-byte cp.async — source byte base 24*u0 is
        // 8-aligned, NOT 16-aligned for odd u0). 128 rows x 24 chunks = 3072 slots.
        {
            const int* uid_t = g_uid_of + t * 256 + m0;
#pragma unroll
            for (int i = 0; i < 12; ++i) {
                int sl = tid + i * 256;
                int r = sl / 24, q2 = sl - r * 24;        // r 0..127, q2 0..23
                int u = __ldg(uid_t + r);
                CP8(gsm + (uint32_t)(r * GPITCH_B + q2 * 8),
                    (const char*)Gu + (size_t)u * (NG * 2) + (size_t)(n0 * 2) + q2 * 8);
            }
        }
        if (s > 0) {
#pragma unroll
            for (int st_ = 0; st_ < 3; ++st_) {
                uint32_t sb = sbase + (uint32_t)st_ * STAGE_BYTES + STAGE_A;
                const char* Bb = Bbase + st_ * 128;
#pragma unroll
                for (int i = 0; i < 3; ++i) {
                    int sl = tid + i * 256;
                    if (sl < 704) {
                        int row = sl >> 3, q = sl & 7;
                        int rs = row < ncols ? row : 0;
                        CP16(sb + (uint32_t)(row * 128) + (((uint32_t)(q * 16)) ^ ((uint32_t)(row & 7) << 4)),
                             Bb + (size_t)rs * 2 * HID + q * 16);
                    }
                }
            }
        }
        asm volatile("cp.async.commit_group;");

        float acc[11][4];
#pragma unroll
        for (int fi = 0; fi < 11; ++fi)
#pragma unroll
            for (int c = 0; c < 4; ++c) acc[fi][c] = 0.f;

        if (s > 0) {
            const int* flg = &g_flag[s - 1][x][0];

            // prologue gate: stages 0..2 cover j 0..191 -> producers 0..6
            {
                int not_ready;
                do {
                    int v = 1;
                    if (tid < 7)
                        asm volatile("ld.acquire.gpu.global.b32 %0, [%1];"
                                     : "=r"(v) : "l"(flg + tid) : "memory");
                    not_ready = __syncthreads_count(v == 0);
                } while (not_ready != 0);
            }

            const __half* Ap = ((s + 1) & 1) ? H1 : H0;
            const char* Abase = (const char*)Ap + (size_t)m0 * 2 * HID;

            auto fillA = [&](int kt) {
                uint32_t sa = sbase + (uint32_t)(kt & 3) * STAGE_BYTES;
                const char* Ab = Abase + kt * 128;
#pragma unroll
                for (int i = 0; i < 4; ++i) {
                    int sl = tid + i * 256;
                    int row = sl >> 3, q = sl & 7;
                    CP16(sa + (uint32_t)(row * 128) + (((uint32_t)(q * 16)) ^ ((uint32_t)(row & 7) << 4)),
                         Ab + (size_t)row * 2 * HID + q * 16);
                }
            };
            auto fillB = [&](int kt) {
                uint32_t sb = sbase + (uint32_t)(kt & 3) * STAGE_BYTES + STAGE_A;
                const char* Bb = Bbase + kt * 128;
#pragma unroll
                for (int i = 0; i < 3; ++i) {
                    int sl = tid + i * 256;
                    if (sl < 704) {
                        int row = sl >> 3, q = sl & 7;
                        int rs = row < ncols ? row : 0;
                        CP16(sb + (uint32_t)(row * 128) + (((uint32_t)(q * 16)) ^ ((uint32_t)(row & 7) << 4)),
                             Bb + (size_t)rs * 2 * HID + q * 16);
                    }
                }
            };

            // A prologue: snapshot slot (j+4)&3 + fillA(j+3), j = -3..-1
#pragma unroll
            for (int j = -3; j < 0; ++j) {
                if (tid < 20)
                    CP16(snap_base + (uint32_t)(((j + 4) & 3) * SNAP_STRIDE + tid * 16),
                         (const char*)flg + tid * 16);
                fillA(j + 3);
                asm volatile("cp.async.commit_group;");
            }

            FragR f[2];
#pragma unroll 1
            for (int kt = 0; kt < 32; ++kt) {
                asm volatile("cp.async.wait_group 2;");
                __syncthreads();

                // ---- compute stage kt ----
                uint32_t stA = sbase + (uint32_t)(kt & 3) * STAGE_BYTES;
                uint32_t stB = stA + STAGE_A;
                {
                    uint32_t ca = akh ^ aswz, cb = bkh ^ bswz;
                    LDSM4(f[0].a, stA + aoff + ca);
#pragma unroll
                    for (int g = 0; g < 6; ++g)
                        LDSM4(f[0].b[g], stB + (uint32_t)((g * 16 + brl) * 128) + cb);
                }
#pragma unroll
                for (int ks = 0; ks < 4; ++ks) {
                    if (ks < 3) {
                        int nb = (ks + 1) & 1;
                        uint32_t ca = (((uint32_t)((ks + 1) * 32)) | akh) ^ aswz;
                        uint32_t cb = (((uint32_t)((ks + 1) * 32)) | bkh) ^ bswz;
                        LDSM4(f[nb].a, stA + aoff + ca);
#pragma unroll
                        for (int g = 0; g < 6; ++g)
                            LDSM4(f[nb].b[g], stB + (uint32_t)((g * 16 + brl) * 128) + cb);
                    }
                    FragR& c = f[ks & 1];
#pragma unroll
                    for (int fi = 0; fi < 11; ++fi)
                        mma_f16(acc[fi], c.a, c.b[fi >> 1][(fi & 1) * 2], c.b[fi >> 1][(fi & 1) * 2 + 1]);
                }

                // ---- gate + refill stage kf = kt+3 ----
                int kf = kt + 3;
                if (kf < 32) {
                    int jlo = kf * 64;
                    int c_lo = c_of(jlo), c_hi = c_of(jlo + 63);
                    const int* sp = snapI + ((kt + 1) & 3) * 80;
                    int ok = 1;
                    for (int c = c_lo; c <= c_hi; ++c) ok &= sp[c];
                    if (!ok) {
                        int span = c_hi - c_lo;
                        int not_ready;
                        do {
                            int v = 1;
                            if (tid <= span)
                                asm volatile("ld.acquire.gpu.global.b32 %0, [%1];"
                                             : "=r"(v) : "l"(flg + c_lo + tid) : "memory");
                            not_ready = __syncthreads_count(v == 0);
                        } while (not_ready != 0);
                    }
                    if (kt <= 25 && tid < 20)
                        CP16(snap_base + (uint32_t)((kt & 3) * SNAP_STRIDE + tid * 16),
                             (const char*)flg + tid * 16);
                    fillA(kf);
                    fillB(kf);
                }
                asm volatile("cp.async.commit_group;");
            }
        } else {
            asm volatile("cp.async.wait_group 0;");
            __syncthreads();
        }

        // ---- stage gates (fp32) into smem, then cell ----
#pragma unroll
        for (int fi = 0; fi < 11; ++fi)
#pragma unroll
            for (int rp = 0; rp < 2; ++rp) {
                int wrow = warp * 16 + (lane >> 2) + rp * 8;
                *(float2*)&Gs[wrow * 92 + fi * 8 + (lane & 3) * 2] =
                    make_float2(acc[fi][rp * 2], acc[fi][rp * 2 + 1]);
            }
        __syncthreads();

        __half* Hout = (s & 1) ? H1 : H0;
        const int hnj = njs >> 1;
        for (int e = tid; e < 128 * hnj; e += 256) {
            int row = e / hnj, p = e - row * hnj;
            int lj = 2 * p;
            int blk = lj >> 2, jj = lj & 3;
            int ci = blk * 12 + jj;
            float gi0 = Gs[row * 92 + ci]     + __half2float(GtH[row * 96 + ci]);
            float gi1 = Gs[row * 92 + ci + 1] + __half2float(GtH[row * 96 + ci + 1]);
            float gg0 = Gs[row * 92 + ci + 4] + __half2float(GtH[row * 96 + ci + 4]);
            float gg1 = Gs[row * 92 + ci + 5] + __half2float(GtH[row * 96 + ci + 5]);
            float go0 = Gs[row * 92 + ci + 8] + __half2float(GtH[row * 96 + ci + 8]);
            float go1 = Gs[row * 92 + ci + 9] + __half2float(GtH[row * 96 + ci + 9]);
            float h0 = sigm(go0) * tanhe(sigm(gi0) * tanhe(gg0));
            float h1 = sigm(go1) * tanhe(sigm(gi1) * tanhe(gg1));
            int j = j0 + lj;
            int row_g = m0 + row;
            if (s < SEQ - 1) {
                *(__half2*)&Hout[(size_t)row_g * HID + j] = __floats2half2_rn(h0, h1);
            } else {
                *(float2*)&out[(size_t)row_g * (2 * HID) + HID + j] = make_float2(h0, h1);
            }
        }
        __syncthreads();                 // gates/G reads done before next prefetch overwrites
        if (tid == 0 && s < SEQ - 1) {
            __threadfence();
            asm volatile("st.release.gpu.global.b32 [%0], %1;"
                         :: "l"(&g_flag[s][x][cwi]), "r"(1) : "memory");
        }
    }
}

// ---------------- launch ----------------
extern "C" void kernel_launch(void* const* d_in, const int* in_sizes, int n_in,
                              void* d_out, int out_size) {
    const int*   inputs = (const int*)d_in[0];
    const float* table  = (const float*)d_in[1];
    const float* Wih_f  = (const float*)d_in[2];
    // d_in[3] = W_hh_f: mathematically unused (forward h = 0)
    const float* bih_f  = (const float*)d_in[4];
    const float* bhh_f  = (const float*)d_in[5];
    const float* Wih_b  = (const float*)d_in[6];
    const float* Whh_b  = (const float*)d_in[7];
    const float* bih_b  = (const float*)d_in[8];
    const float* bhh_b  = (const float*)d_in[9];
    float* out = (float*)d_out;

    __half *Xu, *Xlast, *Gu, *Whh, *Wib, *Wif, *H;
    float *bb, *bf;
    cudaGetSymbolAddress((void**)&Xu,    g_Xu);
    cudaGetSymbolAddress((void**)&Xlast, g_Xlast);
    cudaGetSymbolAddress((void**)&Gu,    g_Gu);
    cudaGetSymbolAddress((void**)&Whh,   g_Whh);
    cudaGetSymbolAddress((void**)&Wib,   g_Wib);
    cudaGetSymbolAddress((void**)&Wif,   g_Wif);
    cudaGetSymbolAddress((void**)&bb,    g_bb);
    cudaGetSymbolAddress((void**)&bf,    g_bf);
    cudaGetSymbolAddress((void**)&H,     g_H);

    cudaFuncSetAttribute(lstm_gemm,  cudaFuncAttributeMaxDynamicSharedMemorySize, GEMM_SMEM);
    cudaFuncSetAttribute(lstm_recur, cudaFuncAttributeMaxDynamicSharedMemorySize, RECUR_SMEM);

    // dedup + prep
    reset_all<<<(VOCAB + 255) / 256, 256>>>();
    claim_tokens<<<NM / 256, 256>>>(inputs);
    map_uid<<<NM / 256, 256>>>(inputs);
    gather_unique<<<NM, 128>>>(table, Xu);
    gather_last<<<BATCH, 128>>>(inputs, table, Xlast);
    pack_weight<<<NG, 128>>>(Whh, Whh_b, HID, 1);
    pack_weight<<<NG, 128>>>(Wib, Wih_b, EMB, 1);
    pack_weight<<<NG, 128>>>(Wif, Wih_f, EMB, 0);
    pack_bias<<<(NG + 255) / 256, 256>>>(bb, bih_b, bhh_b, bf, bih_f, bhh_f);

    // precompute Gu[u][n] (12-packed) for unique tokens only
    lstm_gemm<<<dim3(NG / TN, NM / TM), 256, GEMM_SMEM>>>(
        Xu, EMB, Wib, bb, Gu, nullptr, 0, 0);

    // forward direction (48-packed): single cell on last timestep -> out[:, 0:2048]
    lstm_gemm<<<dim3(BATCH / TM, NG / TN), 256, GEMM_SMEM>>>(
        Xlast, EMB, Wif, bf, nullptr, out, 1, 2 * HID);

    // backward recurrence: 148 resident CTAs (2 slices x 74 panels)
    lstm_recur<<<148, 256, RECUR_SMEM>>>(
        Gu, Whh, H, H + (size_t)BATCH * HID, out);
}

// round 16
// speedup vs baseline: 1.2313x; 1.2313x over previous
#include <cuda_runtime.h>
#include <cuda_fp16.h>
#include <cstdint>

// ---------------- problem constants ----------------
#define VOCAB 50000
#define EMB   1024
#define HID   2048
#define BATCH 256
#define SEQ   128
#define NG    6144   // packed gate cols: band b=0..127 of 16 j's, within band: i(16) g(16) o(16)
#define NM    (BATCH*SEQ)   // 32768 (t,b) positions

// ---------------- GEMM tiling ----------------
#define TM 128
#define TN 96
#define DEPTH 4
#define STAGE_A (128*128)              // 16384 B
#define STAGE_B (96*128)               // 12288 B
#define STAGE_BYTES (STAGE_A+STAGE_B)  // 28672 B
#define GEMM_SMEM (DEPTH*STAGE_BYTES)  // 114688 B
#define GROW_B 208                     // G tile row pitch: 96 halfs (192B) + 16B pad
#define GROW_H 104
#define GTILE_BYTES (128*GROW_B)       // 26624 B
#define SNAP_OFF (GEMM_SMEM + GTILE_BYTES)     // 141312
#define RECUR_SMEM (SNAP_OFF + 4*256)          // 142336

// packed col n -> original weight row:
//   band = n/48, w = n%48, gate = w>>4, jj = w&15, j = band*16+jj
//   wr = j + (gate==0 ? 0 : gate==1 ? 4096 : 6144)   (i, g, o; f-gate unused)

// ---------------- scratch (__device__ globals) ----------------
__device__ __half g_Xu[(size_t)NM * EMB];        // fp16 embeddings per UNIQUE token
__device__ __half g_Xlast[(size_t)BATCH * EMB];  // fp16 embeddings, t = SEQ-1
__device__ __half g_Gu[(size_t)NM * NG];         // gates per unique token, row-major [u][n]
__device__ __half g_Whh[(size_t)NG * HID];       // packed fp16 weights
__device__ __half g_Wib[(size_t)NG * EMB];
__device__ __half g_Wif[(size_t)NG * EMB];
__device__ float  g_bb[NG];
__device__ float  g_bf[NG];
__device__ __half g_H[2][(size_t)BATCH * HID];   // h ping-pong fp16
__device__ int    g_flag[SEQ][2][64];            // per (step, x-group, producer-y) flags
__device__ int    g_mark[VOCAB];
__device__ int    g_uidmap[VOCAB];
__device__ int    g_tok_of[NM];
__device__ int    g_uid_of[NM];
__device__ int    g_nu;

// ---------------- helpers ----------------
__device__ __forceinline__ uint32_t smem_u32(const void* p) {
    uint32_t a;
    asm("{ .reg .u64 t; cvta.to.shared.u64 t, %1; cvt.u32.u64 %0, t; }" : "=r"(a) : "l"(p));
    return a;
}

#define CP16(saddr, gptr) \
    asm volatile("cp.async.cg.shared.global [%0], [%1], 16;" :: "r"(saddr), "l"(gptr))

#define LDSM4(r, a) \
    asm volatile("ldmatrix.sync.aligned.m8n8.x4.shared.b16 {%0,%1,%2,%3}, [%4];" \
        : "=r"((r)[0]), "=r"((r)[1]), "=r"((r)[2]), "=r"((r)[3]) : "r"(a))

__device__ __forceinline__ void mma_f16(float c[4], const uint32_t a[4],
                                        uint32_t b0, uint32_t b1) {
    asm volatile(
        "mma.sync.aligned.m16n8k16.row.col.f32.f16.f16.f32 "
        "{%0,%1,%2,%3},{%4,%5,%6,%7},{%8,%9},{%0,%1,%2,%3};"
        : "+f"(c[0]), "+f"(c[1]), "+f"(c[2]), "+f"(c[3])
        : "r"(a[0]), "r"(a[1]), "r"(a[2]), "r"(a[3]), "r"(b0), "r"(b1));
}

__device__ __forceinline__ float sigm(float x)  { return 1.f / (1.f + __expf(-x)); }
__device__ __forceinline__ float tanhe(float x) { return 2.f / (1.f + __expf(-2.f * x)) - 1.f; }

__device__ __forceinline__ int gate_row(int n) {
    int band = n / 48, w = n - band * 48;
    int gate = w >> 4, jj = w & 15;
    return band * 16 + jj + (gate == 0 ? 0 : (gate == 1 ? 4096 : 6144));
}

// ---------------- dedup kernels ----------------
__global__ void reset_all() {
    int i = blockIdx.x * 256 + threadIdx.x;
    if (i < VOCAB) g_mark[i] = 0;
    if (i < SEQ * 2 * 64) ((int*)g_flag)[i] = 0;
    if (i == 0) g_nu = 0;
}

__global__ void claim_tokens(const int* __restrict__ idx) {
    int m = blockIdx.x * 256 + threadIdx.x;   // m = t*256 + b
    int t = m >> 8, b = m & 255;
    int tok = idx[b * SEQ + t];
    if ((unsigned)tok >= (unsigned)VOCAB) tok = 0;
    if (atomicCAS(&g_mark[tok], 0, 1) == 0) {
        int u = atomicAdd(&g_nu, 1);
        g_uidmap[tok] = u;
        g_tok_of[u] = tok;
    }
}

__global__ void map_uid(const int* __restrict__ idx) {
    int m = blockIdx.x * 256 + threadIdx.x;
    int t = m >> 8, b = m & 255;
    int tok = idx[b * SEQ + t];
    if ((unsigned)tok >= (unsigned)VOCAB) tok = 0;
    g_uid_of[m] = g_uidmap[tok];
}

// copy one embedding row (fp32 -> fp16), 128 threads
__device__ __forceinline__ void copy_row_f2h(const float* __restrict__ src,
                                             __half* __restrict__ dst) {
    const float4* s = (const float4*)src + threadIdx.x * 2;
    float4 v0 = s[0], v1 = s[1];
    __half2 h0 = __floats2half2_rn(v0.x, v0.y), h1 = __floats2half2_rn(v0.z, v0.w);
    __half2 h2 = __floats2half2_rn(v1.x, v1.y), h3 = __floats2half2_rn(v1.z, v1.w);
    ((uint4*)dst)[threadIdx.x] =
        make_uint4(*(uint32_t*)&h0, *(uint32_t*)&h1, *(uint32_t*)&h2, *(uint32_t*)&h3);
}

// fused: blocks [0,NM) gather unique-token rows; blocks [NM, NM+BATCH) gather t=SEQ-1 rows
__global__ void gather_embeds(const int* __restrict__ idx, const float* __restrict__ table,
                              __half* __restrict__ dstU, __half* __restrict__ dstL) {
    int u = blockIdx.x;
    if (u < NM) {
        if (u >= g_nu) return;
        copy_row_f2h(table + (size_t)g_tok_of[u] * EMB, dstU + (size_t)u * EMB);
    } else {
        int b = u - NM;
        int row = idx[b * SEQ + (SEQ - 1)];
        if ((unsigned)row >= (unsigned)VOCAB) row = 0;
        copy_row_f2h(table + (size_t)row * EMB, dstL + (size_t)b * EMB);
    }
}

// fused weight pack: grid.y selects {0: Whh(K=HID), 1: Wib(K=EMB), 2: Wif(K=EMB)}
__global__ void pack_weight3(__half* __restrict__ dWhh, const float* __restrict__ sWhh,
                             __half* __restrict__ dWib, const float* __restrict__ sWib,
                             __half* __restrict__ dWif, const float* __restrict__ sWif) {
    int n = blockIdx.x;
    int which = blockIdx.y;
    int wr = gate_row(n);
    int K = (which == 0) ? HID : EMB;
    const float* src = (which == 0) ? sWhh : (which == 1) ? sWib : sWif;
    __half*      dstp = (which == 0) ? dWhh : (which == 1) ? dWib : dWif;
    const float4* s = (const float4*)(src + (size_t)wr * K);
    uint4* d = (uint4*)(dstp + (size_t)n * K);
    for (int i = threadIdx.x; i < (K >> 3); i += blockDim.x) {
        float4 a = s[i * 2], b = s[i * 2 + 1];
        __half2 h0 = __floats2half2_rn(a.x, a.y), h1 = __floats2half2_rn(a.z, a.w);
        __half2 h2 = __floats2half2_rn(b.x, b.y), h3 = __floats2half2_rn(b.z, b.w);
        d[i] = make_uint4(*(uint32_t*)&h0, *(uint32_t*)&h1, *(uint32_t*)&h2, *(uint32_t*)&h3);
    }
}

__global__ void pack_bias(float* __restrict__ db, const float* __restrict__ bi_b, const float* __restrict__ bh_b,
                          float* __restrict__ df, const float* __restrict__ bi_f, const float* __restrict__ bh_f) {
    int n = blockIdx.x * blockDim.x + threadIdx.x;
    if (n >= NG) return;
    int wr = gate_row(n);
    db[n] = bi_b[wr] + bh_b[wr];
    df[n] = bi_f[wr] + bh_f[wr];
}

// ---------------- fragments ----------------
struct Frag { uint32_t a0[4], a1[4], b0[4], b1[4], b2[4]; };

// ---------------- one-shot GEMM (precompute / forward cell) ----------------
// mode 0: grid (n-panels, m-panels over unique rows); early-exits panels >= g_nu;
//         writes fp16 Gu[u][n] = C + bias[n] (row-major).
// mode 1: grid (m-panels, n-panels); register-local cell; fp32 h -> fout (ld=out_ld).
__global__ __launch_bounds__(256) void lstm_gemm(
    const __half* __restrict__ A, int K, const __half* __restrict__ W,
    const float* __restrict__ bias,
    __half* __restrict__ gout, float* __restrict__ fout,
    int mode, int out_ld)
{
    extern __shared__ char smem[];
    const uint32_t sbase = smem_u32(smem);
    const int tid = threadIdx.x;
    const int lane = tid & 31, warp = tid >> 5;
    const int gid = lane >> 2, tig = lane & 3;
    const int wm = warp & 3, wn = warp >> 2;
    const int bm = (mode == 0) ? blockIdx.y : blockIdx.x;
    const int bn = (mode == 0) ? blockIdx.x : blockIdx.y;
    const int m0 = bm * TM;
    const int j0 = bn * TN;

    if (mode == 0 && m0 >= g_nu) return;   // panel entirely beyond unique rows

    float acc[2][6][4];
#pragma unroll
    for (int mt = 0; mt < 2; ++mt)
#pragma unroll
        for (int nt = 0; nt < 6; ++nt)
#pragma unroll
            for (int c = 0; c < 4; ++c) acc[mt][nt][c] = 0.f;

    const int ar = wm * 32 + (lane & 15);
    const uint32_t aoff0 = (uint32_t)ar * 128u, aoff1 = aoff0 + 2048u;
    const uint32_t aswz  = (uint32_t)(ar & 7) << 4;
    const uint32_t akh   = ((lane >> 4) & 1) << 4;
    const int brb = wn * 48 + (lane & 7) + ((lane >> 4) << 3);
    const uint32_t bswz = (uint32_t)(brb & 7) << 4;
    const uint32_t bkh  = ((lane >> 3) & 1) << 4;
    const uint32_t boff0 = (uint32_t)brb * 128u, boff1 = boff0 + 2048u, boff2 = boff0 + 4096u;

    const int nkt = K >> 6;
    const char* Abase = (const char*)A + (size_t)m0 * 2 * K;
    const char* Bbase = (const char*)W + (size_t)j0 * 2 * K;

    auto fill = [&](int kt) {
        uint32_t st = sbase + (uint32_t)(kt & 3) * STAGE_BYTES;
        const char* Ab = Abase + kt * 128;
        const char* Bb = Bbase + kt * 128;
#pragma unroll
        for (int i = 0; i < 4; ++i) {
            int s = tid + i * 256;
            int row = s >> 3, q = s & 7;
            CP16(st + (uint32_t)(row * 128) + (((uint32_t)(q * 16)) ^ ((uint32_t)(row & 7) << 4)),
                 Ab + (size_t)row * 2 * K + q * 16);
        }
        uint32_t stb = st + STAGE_A;
#pragma unroll
        for (int i = 0; i < 3; ++i) {
            int s = tid + i * 256;
            int row = s >> 3, q = s & 7;
            CP16(stb + (uint32_t)(row * 128) + (((uint32_t)(q * 16)) ^ ((uint32_t)(row & 7) << 4)),
                 Bb + (size_t)row * 2 * K + q * 16);
        }
    };

#pragma unroll
    for (int p = 0; p < DEPTH - 1; ++p) {
        if (p < nkt) fill(p);
        asm volatile("cp.async.commit_group;");
    }

    Frag f[2];
#pragma unroll 1
    for (int kt = 0; kt < nkt; ++kt) {
        asm volatile("cp.async.wait_group %0;" :: "n"(DEPTH - 2));
        __syncthreads();
        if (kt + DEPTH - 1 < nkt) fill(kt + DEPTH - 1);
        asm volatile("cp.async.commit_group;");

        uint32_t st  = sbase + (uint32_t)(kt & 3) * STAGE_BYTES;
        uint32_t stB = st + STAGE_A;
        {
            uint32_t ca = akh ^ aswz, cb = bkh ^ bswz;
            LDSM4(f[0].a0, st + aoff0 + ca);  LDSM4(f[0].a1, st + aoff1 + ca);
            LDSM4(f[0].b0, stB + boff0 + cb); LDSM4(f[0].b1, stB + boff1 + cb); LDSM4(f[0].b2, stB + boff2 + cb);
        }
#pragma unroll
        for (int ks = 0; ks < 4; ++ks) {
            if (ks < 3) {
                int nb = (ks + 1) & 1;
                uint32_t ca = (((uint32_t)((ks + 1) * 32)) | akh) ^ aswz;
                uint32_t cb = (((uint32_t)((ks + 1) * 32)) | bkh) ^ bswz;
                LDSM4(f[nb].a0, st + aoff0 + ca);  LDSM4(f[nb].a1, st + aoff1 + ca);
                LDSM4(f[nb].b0, stB + boff0 + cb); LDSM4(f[nb].b1, stB + boff1 + cb); LDSM4(f[nb].b2, stB + boff2 + cb);
            }
            Frag& c = f[ks & 1];
            mma_f16(acc[0][0], c.a0, c.b0[0], c.b0[1]);  mma_f16(acc[1][0], c.a1, c.b0[0], c.b0[1]);
            mma_f16(acc[0][1], c.a0, c.b0[2], c.b0[3]);  mma_f16(acc[1][1], c.a1, c.b0[2], c.b0[3]);
            mma_f16(acc[0][2], c.a0, c.b1[0], c.b1[1]);  mma_f16(acc[1][2], c.a1, c.b1[0], c.b1[1]);
            mma_f16(acc[0][3], c.a0, c.b1[2], c.b1[3]);  mma_f16(acc[1][3], c.a1, c.b1[2], c.b1[3]);
            mma_f16(acc[0][4], c.a0, c.b2[0], c.b2[1]);  mma_f16(acc[1][4], c.a1, c.b2[0], c.b2[1]);
            mma_f16(acc[0][5], c.a0, c.b2[2], c.b2[3]);  mma_f16(acc[1][5], c.a1, c.b2[2], c.b2[3]);
        }
    }

    if (mode == 0) {
#pragma unroll
        for (int mt = 0; mt < 2; ++mt)
#pragma unroll
            for (int nt = 0; nt < 6; ++nt) {
                int u = m0 + wm * 32 + mt * 16 + gid;
                int n = j0 + wn * 48 + nt * 8 + tig * 2;
                float bv0 = bias[n], bv1 = bias[n + 1];
                __half2 v0 = __floats2half2_rn(acc[mt][nt][0] + bv0, acc[mt][nt][1] + bv1);
                __half2 v1 = __floats2half2_rn(acc[mt][nt][2] + bv0, acc[mt][nt][3] + bv1);
                *(__half2*)&gout[(size_t)u * NG + n]       = v0;
                *(__half2*)&gout[(size_t)(u + 8) * NG + n] = v1;
            }
    } else {
        // register-local cell: acc[mt][jh]=i, acc[mt][2+jh]=g, acc[mt][4+jh]=o
#pragma unroll
        for (int mt = 0; mt < 2; ++mt)
#pragma unroll
            for (int jh = 0; jh < 2; ++jh)
#pragma unroll
                for (int rp = 0; rp < 2; ++rp) {
                    int row = m0 + wm * 32 + mt * 16 + gid + rp * 8;
                    int nb = j0 + wn * 48 + jh * 8 + tig * 2;
                    float hv[2];
#pragma unroll
                    for (int col = 0; col < 2; ++col) {
                        float gi = acc[mt][jh][rp * 2 + col]     + bias[nb + col];
                        float gg = acc[mt][2 + jh][rp * 2 + col] + bias[nb + 16 + col];
                        float go = acc[mt][4 + jh][rp * 2 + col] + bias[nb + 32 + col];
                        hv[col] = sigm(go) * tanhe(sigm(gi) * tanhe(gg));
                    }
                    int j = bn * 32 + wn * 16 + jh * 8 + tig * 2;
                    *(float2*)&fout[(size_t)row * out_ld + j] = make_float2(hv[0], hv[1]);
                }
    }
}

// ---------------- persistent recurrence kernel ----------------
// 128 CTAs (grid 2x64), 1/SM. Fine-grained producer gating via cp.async flag
// snapshots; G tile fetched per-row INDIRECTLY from Gu via uid_of (dedup).
__global__ __launch_bounds__(256, 1) void lstm_recur(
    const __half* __restrict__ Gu, const __half* __restrict__ W,
    __half* __restrict__ H0, __half* __restrict__ H1, float* __restrict__ out)
{
    extern __shared__ char smem[];
    const uint32_t sbase = smem_u32(smem);
    const uint32_t gsm = sbase + GEMM_SMEM;
    __half* GsmH = (__half*)(smem + GEMM_SMEM);
    const uint32_t snap_base = sbase + SNAP_OFF;
    const int* snapI = (const int*)(smem + SNAP_OFF);
    const int tid = threadIdx.x;
    const int lane = tid & 31, warp = tid >> 5;
    const int gid = lane >> 2, tig = lane & 3;
    const int wm = warp & 3, wn = warp >> 2;
    const int x = blockIdx.x, y = blockIdx.y;
    const int m0 = x * TM, j0 = y * TN;

    const int ar = wm * 32 + (lane & 15);
    const uint32_t aoff0 = (uint32_t)ar * 128u, aoff1 = aoff0 + 2048u;
    const uint32_t aswz  = (uint32_t)(ar & 7) << 4;
    const uint32_t akh   = ((lane >> 4) & 1) << 4;
    const int brb = wn * 48 + (lane & 7) + ((lane >> 4) << 3);
    const uint32_t bswz = (uint32_t)(brb & 7) << 4;
    const uint32_t bkh  = ((lane >> 3) & 1) << 4;
    const uint32_t boff0 = (uint32_t)brb * 128u, boff1 = boff0 + 2048u, boff2 = boff0 + 4096u;

    const char* Bbase = (const char*)W + (size_t)j0 * 2 * HID;

#pragma unroll 1
    for (int s = 0; s < SEQ; ++s) {
        const int t = (SEQ - 1) - s;

        // group 0: G tile (indirect rows from Gu) + (s>0) W stages 0..2
        {
            const int* uid_t = g_uid_of + t * 256 + m0;
#pragma unroll
            for (int i = 0; i < 6; ++i) {                 // 128 rows x 12 chunks = 1536
                int sl = tid + i * 256;
                int r = sl / 12, q = sl - r * 12;
                int u = __ldg(uid_t + r);
                CP16(gsm + (uint32_t)(r * GROW_B + q * 16),
                     (const char*)Gu + (size_t)u * (NG * 2) + (size_t)(j0 * 2) + q * 16);
            }
        }
        if (s > 0) {
#pragma unroll
            for (int st_ = 0; st_ < 3; ++st_) {
                uint32_t sb = sbase + (uint32_t)st_ * STAGE_BYTES + STAGE_A;
                const char* Bb = Bbase + st_ * 128;
#pragma unroll
                for (int i = 0; i < 3; ++i) {
                    int sl = tid + i * 256;
                    int row = sl >> 3, q = sl & 7;
                    CP16(sb + (uint32_t)(row * 128) + (((uint32_t)(q * 16)) ^ ((uint32_t)(row & 7) << 4)),
                         Bb + (size_t)row * 2 * HID + q * 16);
                }
            }
        }
        asm volatile("cp.async.commit_group;");

        float acc[2][6][4];
#pragma unroll
        for (int mt = 0; mt < 2; ++mt)
#pragma unroll
            for (int nt = 0; nt < 6; ++nt)
#pragma unroll
                for (int c = 0; c < 4; ++c) acc[mt][nt][c] = 0.f;

        if (s > 0) {
            const int* flg = &g_flag[s - 1][x][0];

            // gate only on producers y0..5 (needed by prologue stages 0..2)
            {
                int not_ready;
                do {
                    int v = 1;
                    if (tid < 6)
                        asm volatile("ld.acquire.gpu.global.b32 %0, [%1];"
                                     : "=r"(v) : "l"(flg + tid) : "memory");
                    not_ready = __syncthreads_count(v == 0);
                } while (not_ready != 0);
            }

            const __half* Ap = ((s + 1) & 1) ? H1 : H0;
            const char* Abase = (const char*)Ap + (size_t)m0 * 2 * HID;

            auto fillA = [&](int kt) {
                uint32_t sa = sbase + (uint32_t)(kt & 3) * STAGE_BYTES;
                const char* Ab = Abase + kt * 128;
#pragma unroll
                for (int i = 0; i < 4; ++i) {
                    int sl = tid + i * 256;
                    int row = sl >> 3, q = sl & 7;
                    CP16(sa + (uint32_t)(row * 128) + (((uint32_t)(q * 16)) ^ ((uint32_t)(row & 7) << 4)),
                         Ab + (size_t)row * 2 * HID + q * 16);
                }
            };
            auto fillB = [&](int kt) {
                uint32_t sb = sbase + (uint32_t)(kt & 3) * STAGE_BYTES + STAGE_A;
                const char* Bb = Bbase + kt * 128;
#pragma unroll
                for (int i = 0; i < 3; ++i) {
                    int sl = tid + i * 256;
                    int row = sl >> 3, q = sl & 7;
                    CP16(sb + (uint32_t)(row * 128) + (((uint32_t)(q * 16)) ^ ((uint32_t)(row & 7) << 4)),
                         Bb + (size_t)row * 2 * HID + q * 16);
                }
            };

            // A prologue: snapshot (slot (j+4)&3) + fillA(j+3), j=-3..-1
#pragma unroll
            for (int j = -3; j < 0; ++j) {
                if (tid < 16)
                    CP16(snap_base + (uint32_t)(((j + 4) & 3) * 256 + tid * 16),
                         (const char*)flg + tid * 16);
                fillA(j + 3);
                asm volatile("cp.async.commit_group;");
            }

            Frag f[2];
#pragma unroll 1
            for (int kt = 0; kt < 32; ++kt) {
                asm volatile("cp.async.wait_group 2;");
                __syncthreads();

                // ---- compute stage kt ----
                uint32_t st  = sbase + (uint32_t)(kt & 3) * STAGE_BYTES;
                uint32_t stB = st + STAGE_A;
                {
                    uint32_t ca = akh ^ aswz, cb = bkh ^ bswz;
                    LDSM4(f[0].a0, st + aoff0 + ca);  LDSM4(f[0].a1, st + aoff1 + ca);
                    LDSM4(f[0].b0, stB + boff0 + cb); LDSM4(f[0].b1, stB + boff1 + cb); LDSM4(f[0].b2, stB + boff2 + cb);
                }
#pragma unroll
                for (int ks = 0; ks < 4; ++ks) {
                    if (ks < 3) {
                        int nb = (ks + 1) & 1;
                        uint32_t ca = (((uint32_t)((ks + 1) * 32)) | akh) ^ aswz;
                        uint32_t cb = (((uint32_t)((ks + 1) * 32)) | bkh) ^ bswz;
                        LDSM4(f[nb].a0, st + aoff0 + ca);  LDSM4(f[nb].a1, st + aoff1 + ca);
                        LDSM4(f[nb].b0, stB + boff0 + cb); LDSM4(f[nb].b1, stB + boff1 + cb); LDSM4(f[nb].b2, stB + boff2 + cb);
                    }
                    Frag& c = f[ks & 1];
                    mma_f16(acc[0][0], c.a0, c.b0[0], c.b0[1]);  mma_f16(acc[1][0], c.a1, c.b0[0], c.b0[1]);
                    mma_f16(acc[0][1], c.a0, c.b0[2], c.b0[3]);  mma_f16(acc[1][1], c.a1, c.b0[2], c.b0[3]);
                    mma_f16(acc[0][2], c.a0, c.b1[0], c.b1[1]);  mma_f16(acc[1][2], c.a1, c.b1[0], c.b1[1]);
                    mma_f16(acc[0][3], c.a0, c.b1[2], c.b1[3]);  mma_f16(acc[1][3], c.a1, c.b1[2], c.b1[3]);
                    mma_f16(acc[0][4], c.a0, c.b2[0], c.b2[1]);  mma_f16(acc[1][4], c.a1, c.b2[0], c.b2[1]);
                    mma_f16(acc[0][5], c.a0, c.b2[2], c.b2[3]);  mma_f16(acc[1][5], c.a1, c.b2[2], c.b2[3]);
                }

                // ---- gate + refill stage kf = kt+3 ----
                int kf = kt + 3;
                if (kf < 32) {
                    int r0 = snapI[((kt + 1) & 3) * 64 + 2 * kf];
                    int r1 = snapI[((kt + 1) & 3) * 64 + 2 * kf + 1];
                    if (!(r0 && r1)) {                 // snapshot stale -> spin fallback
                        int not_ready;
                        do {
                            int v = 1;
                            if (tid < 2)
                                asm volatile("ld.acquire.gpu.global.b32 %0, [%1];"
                                             : "=r"(v) : "l"(flg + 2 * kf + tid) : "memory");
                            not_ready = __syncthreads_count(v == 0);
                        } while (not_ready != 0);
                    }
                    if (kt <= 25 && tid < 16)          // refresh snapshot (slot kt&3)
                        CP16(snap_base + (uint32_t)((kt & 3) * 256 + tid * 16),
                             (const char*)flg + tid * 16);
                    fillA(kf);
                    fillB(kf);
                }
                asm volatile("cp.async.commit_group;");
            }
        } else {
            asm volatile("cp.async.wait_group 0;");
            __syncthreads();
        }

        // ---- register-local cell epilogue (G addend from smem tile) ----
        __half* Hout = (s & 1) ? H1 : H0;
#pragma unroll
        for (int mt = 0; mt < 2; ++mt)
#pragma unroll
            for (int jh = 0; jh < 2; ++jh)
#pragma unroll
                for (int rp = 0; rp < 2; ++rp) {
                    int rl = wm * 32 + mt * 16 + gid + rp * 8;
                    int nb = wn * 48 + jh * 8 + tig * 2;
                    float2 giF = __half22float2(*(const __half2*)&GsmH[rl * GROW_H + nb]);
                    float2 ggF = __half22float2(*(const __half2*)&GsmH[rl * GROW_H + nb + 16]);
                    float2 goF = __half22float2(*(const __half2*)&GsmH[rl * GROW_H + nb + 32]);
                    float hv[2];
#pragma unroll
                    for (int col = 0; col < 2; ++col) {
                        float gi = acc[mt][jh][rp * 2 + col]     + (col ? giF.y : giF.x);
                        float gg = acc[mt][2 + jh][rp * 2 + col] + (col ? ggF.y : ggF.x);
                        float go = acc[mt][4 + jh][rp * 2 + col] + (col ? goF.y : goF.x);
                        hv[col] = sigm(go) * tanhe(sigm(gi) * tanhe(gg));
                    }
                    int j = y * 32 + wn * 16 + jh * 8 + tig * 2;
                    int row = m0 + rl;
                    if (s < SEQ - 1) {
                        *(__half2*)&Hout[(size_t)row * HID + j] = __floats2half2_rn(hv[0], hv[1]);
                    } else {
                        *(float2*)&out[(size_t)row * (2 * HID) + HID + j] = make_float2(hv[0], hv[1]);
                    }
                }
        __syncthreads();                 // GsmH reads + stage reads complete before next prefetch
        if (tid == 0 && s < SEQ - 1) {
            __threadfence();             // publish ALL warps' H stores at gpu scope
            asm volatile("st.release.gpu.global.b32 [%0], %1;"
                         :: "l"(&g_flag[s][x][y]), "r"(1) : "memory");
        }
    }
}

// ---------------- launch ----------------
extern "C" void kernel_launch(void* const* d_in, const int* in_sizes, int n_in,
                              void* d_out, int out_size) {
    const int*   inputs = (const int*)d_in[0];
    const float* table  = (const float*)d_in[1];
    const float* Wih_f  = (const float*)d_in[2];
    // d_in[3] = W_hh_f: mathematically unused (forward h = 0)
    const float* bih_f  = (const float*)d_in[4];
    const float* bhh_f  = (const float*)d_in[5];
    const float* Wih_b  = (const float*)d_in[6];
    const float* Whh_b  = (const float*)d_in[7];
    const float* bih_b  = (const float*)d_in[8];
    const float* bhh_b  = (const float*)d_in[9];
    float* out = (float*)d_out;

    __half *Xu, *Xlast, *Gu, *Whh, *Wib, *Wif, *H;
    float *bb, *bf;
    cudaGetSymbolAddress((void**)&Xu,    g_Xu);
    cudaGetSymbolAddress((void**)&Xlast, g_Xlast);
    cudaGetSymbolAddress((void**)&Gu,    g_Gu);
    cudaGetSymbolAddress((void**)&Whh,   g_Whh);
    cudaGetSymbolAddress((void**)&Wib,   g_Wib);
    cudaGetSymbolAddress((void**)&Wif,   g_Wif);
    cudaGetSymbolAddress((void**)&bb,    g_bb);
    cudaGetSymbolAddress((void**)&bf,    g_bf);
    cudaGetSymbolAddress((void**)&H,     g_H);

    cudaFuncSetAttribute(lstm_gemm,  cudaFuncAttributeMaxDynamicSharedMemorySize, GEMM_SMEM);
    cudaFuncSetAttribute(lstm_recur, cudaFuncAttributeMaxDynamicSharedMemorySize, RECUR_SMEM);

    // dedup + prep (fused launches)
    reset_all<<<(VOCAB + 255) / 256, 256>>>();
    claim_tokens<<<NM / 256, 256>>>(inputs);
    map_uid<<<NM / 256, 256>>>(inputs);
    gather_embeds<<<NM + BATCH, 128>>>(inputs, table, Xu, Xlast);
    pack_weight3<<<dim3(NG, 3), 128>>>(Whh, Whh_b, Wib, Wih_b, Wif, Wih_f);
    pack_bias<<<(NG + 255) / 256, 256>>>(bb, bih_b, bhh_b, bf, bih_f, bhh_f);

    // precompute Gu[u][n] for unique tokens only (early-exit panels beyond g_nu)
    lstm_gemm<<<dim3(NG / TN, NM / TM), 256, GEMM_SMEM>>>(
        Xu, EMB, Wib, bb, Gu, nullptr, 0, 0);

    // forward direction: single cell on last timestep, h=c=0 -> out[:, 0:2048]
    lstm_gemm<<<dim3(BATCH / TM, NG / TN), 256, GEMM_SMEM>>>(
        Xlast, EMB, Wif, bf, nullptr, out, 1, 2 * HID);

    // backward recurrence: one persistent kernel, 128 resident CTAs
    lstm_recur<<<dim3(2, 64), 256, RECUR_SMEM>>>(
        Gu, Whh, H, H + (size_t)BATCH * HID, out);
}